// round 2
// baseline (speedup 1.0000x reference)
#include <cuda_runtime.h>
#include <cuda_fp16.h>

// Bidirectional LSTM (H=128, I=4, B=256, T=512), final hidden states only.
// out: [B, 2H] fp32.  Grid: 128 CTAs = 2 dirs x 64 batch-tiles (Bt=4).
// Thread g (0..511) owns gate row g. Whh lives in SMEM as fp16 (conflict-free
// pitch). h, c, accumulation all fp32. Activations via ex2/rcp (accurate).

#define HD    128
#define G4    512
#define BTOT  256
#define TLEN  512
#define IDIM  4
#define BT    4
#define NTH   512
#define WPITCH 130   // halves per weight row: 260 B -> lane g hits bank (g+k)%32

// SMEM layout (bytes)
#define W_SM_BYTES   (G4 * WPITCH * 2)          // 133120
#define X_SM_BYTES   (TLEN * BT * IDIM * 4)     // 32768
#define GATE_BYTES   (G4 * 16)                  // 8192
#define H_SM_BYTES   (HD * 16)                  // 2048
#define X_SM_OFF     (W_SM_BYTES)
#define GATE_OFF     (W_SM_BYTES + X_SM_BYTES)
#define H_SM_OFF     (GATE_OFF + GATE_BYTES)
#define SMEM_BYTES   (H_SM_OFF + H_SM_BYTES)    // 176128

__device__ __forceinline__ float sigmoid_f(float x) {
    // 1/(1+e^-x). e overflow (x<-88) -> inf -> result 0: correct limit.
    float e = __expf(-x);
    return __fdividef(1.0f, 1.0f + e);
}

__device__ __forceinline__ float tanh_f(float x) {
    // tanh(|x|) = (1-e)/(1+e), e = exp(-2|x|) in (0,1] -> no overflow; restore sign.
    float ax = fabsf(x);
    float e = __expf(-2.0f * ax);
    float t = __fdividef(1.0f - e, 1.0f + e);
    return copysignf(t, x);
}

__global__ void __launch_bounds__(NTH, 1)
lstm_bidir_kernel(const float* __restrict__ x,
                  const float* __restrict__ Wih_f, const float* __restrict__ Whh_f,
                  const float* __restrict__ bih_f, const float* __restrict__ bhh_f,
                  const float* __restrict__ Wih_b, const float* __restrict__ Whh_b,
                  const float* __restrict__ bih_b, const float* __restrict__ bhh_b,
                  float* __restrict__ out)
{
    extern __shared__ unsigned char smem_raw[];
    __half*  W_sm     = reinterpret_cast<__half*>(smem_raw);
    float*   x_sm     = reinterpret_cast<float*>(smem_raw + X_SM_OFF);
    float4*  gates_sm = reinterpret_cast<float4*>(smem_raw + GATE_OFF);
    float4*  h_sm     = reinterpret_cast<float4*>(smem_raw + H_SM_OFF);

    const int tid = threadIdx.x;
    const int bx  = blockIdx.x;
    const int dir = bx >> 6;            // 0 = forward, 1 = backward
    const int b_base = (bx & 63) * BT;

    const float* Wih = dir ? Wih_b : Wih_f;
    const float* Whh = dir ? Whh_b : Whh_f;
    const float* bih = dir ? bih_b : bih_f;
    const float* bhh = dir ? bhh_b : bhh_f;

    // ---- Stage Whh into SMEM as fp16 (coalesced global reads) ----
    for (int idx = tid; idx < G4 * HD; idx += NTH) {
        int g = idx >> 7;
        int k = idx & 127;
        W_sm[g * WPITCH + k] = __float2half_rn(Whh[idx]);
    }
    // ---- Stage this CTA's x slice: x_sm[t][b][i] ----
    for (int idx = tid; idx < BT * TLEN * IDIM; idx += NTH) {
        int b = idx >> 11;          // / (TLEN*IDIM)
        int r = idx & 2047;         // t*4 + i
        x_sm[(r >> 2) * (BT * IDIM) + b * IDIM + (r & 3)] =
            x[(b_base + b) * (TLEN * IDIM) + r];
    }
    // ---- Per-thread gate-row constants ----
    const int g = tid;
    float4 wi = *reinterpret_cast<const float4*>(Wih + g * IDIM);
    float bias = bih[g] + bhh[g];

    if (tid < HD) h_sm[tid] = make_float4(0.f, 0.f, 0.f, 0.f);
    float c0 = 0.f, c1 = 0.f, c2 = 0.f, c3 = 0.f;
    float h0 = 0.f, h1 = 0.f, h2 = 0.f, h3 = 0.f;
    __syncthreads();

    const __half* wrow = W_sm + g * WPITCH;

    for (int t = 0; t < TLEN; t++) {
        const int tx = dir ? (TLEN - 1 - t) : t;

        // xw + bias init (I=4 folded in, ~3% of step cost)
        const float4* xr = reinterpret_cast<const float4*>(x_sm + tx * (BT * IDIM));
        float4 xb0 = xr[0], xb1 = xr[1], xb2 = xr[2], xb3 = xr[3];
        float a0 = fmaf(xb0.x, wi.x, fmaf(xb0.y, wi.y, fmaf(xb0.z, wi.z, fmaf(xb0.w, wi.w, bias))));
        float a1 = fmaf(xb1.x, wi.x, fmaf(xb1.y, wi.y, fmaf(xb1.z, wi.z, fmaf(xb1.w, wi.w, bias))));
        float a2 = fmaf(xb2.x, wi.x, fmaf(xb2.y, wi.y, fmaf(xb2.z, wi.z, fmaf(xb2.w, wi.w, bias))));
        float a3 = fmaf(xb3.x, wi.x, fmaf(xb3.y, wi.y, fmaf(xb3.z, wi.z, fmaf(xb3.w, wi.w, bias))));

        // Main matvec: gates[g][b] += sum_k h[b][k] * Whh[g][k]
        #pragma unroll 16
        for (int k = 0; k < HD; k += 2) {
            __half2 w2 = *reinterpret_cast<const __half2*>(wrow + k);
            float wA = __low2float(w2);
            float wB = __high2float(w2);
            float4 ha = h_sm[k];
            float4 hb = h_sm[k + 1];
            a0 = fmaf(ha.x, wA, a0);
            a1 = fmaf(ha.y, wA, a1);
            a2 = fmaf(ha.z, wA, a2);
            a3 = fmaf(ha.w, wA, a3);
            a0 = fmaf(hb.x, wB, a0);
            a1 = fmaf(hb.y, wB, a1);
            a2 = fmaf(hb.z, wB, a2);
            a3 = fmaf(hb.w, wB, a3);
        }
        gates_sm[g] = make_float4(a0, a1, a2, a3);
        __syncthreads();

        // Epilogue: threads 0..127 own hidden unit j=tid for all 4 batches.
        if (tid < HD) {
            float4 gi = gates_sm[tid];
            float4 gf = gates_sm[tid + 128];
            float4 gc = gates_sm[tid + 256];
            float4 go = gates_sm[tid + 384];
            {
                float iv = sigmoid_f(gi.x), fv = sigmoid_f(gf.x);
                float gv = tanh_f(gc.x),    ov = sigmoid_f(go.x);
                c0 = fmaf(fv, c0, iv * gv); h0 = ov * tanh_f(c0);
            }
            {
                float iv = sigmoid_f(gi.y), fv = sigmoid_f(gf.y);
                float gv = tanh_f(gc.y),    ov = sigmoid_f(go.y);
                c1 = fmaf(fv, c1, iv * gv); h1 = ov * tanh_f(c1);
            }
            {
                float iv = sigmoid_f(gi.z), fv = sigmoid_f(gf.z);
                float gv = tanh_f(gc.z),    ov = sigmoid_f(go.z);
                c2 = fmaf(fv, c2, iv * gv); h2 = ov * tanh_f(c2);
            }
            {
                float iv = sigmoid_f(gi.w), fv = sigmoid_f(gf.w);
                float gv = tanh_f(gc.w),    ov = sigmoid_f(go.w);
                c3 = fmaf(fv, c3, iv * gv); h3 = ov * tanh_f(c3);
            }
            h_sm[tid] = make_float4(h0, h1, h2, h3);
        }
        __syncthreads();
    }

    // Final h -> out[b][dir*128 + j]
    if (tid < HD) {
        const int col = dir * HD + tid;
        out[(b_base + 0) * (2 * HD) + col] = h0;
        out[(b_base + 1) * (2 * HD) + col] = h1;
        out[(b_base + 2) * (2 * HD) + col] = h2;
        out[(b_base + 3) * (2 * HD) + col] = h3;
    }
}

extern "C" void kernel_launch(void* const* d_in, const int* in_sizes, int n_in,
                              void* d_out, int out_size)
{
    const float* x     = (const float*)d_in[0];
    const float* Wih_f = (const float*)d_in[1];
    const float* Whh_f = (const float*)d_in[2];
    const float* bih_f = (const float*)d_in[3];
    const float* bhh_f = (const float*)d_in[4];
    const float* Wih_b = (const float*)d_in[5];
    const float* Whh_b = (const float*)d_in[6];
    const float* bih_b = (const float*)d_in[7];
    const float* bhh_b = (const float*)d_in[8];
    float* out = (float*)d_out;

    cudaFuncSetAttribute(lstm_bidir_kernel,
                         cudaFuncAttributeMaxDynamicSharedMemorySize, SMEM_BYTES);

    lstm_bidir_kernel<<<128, NTH, SMEM_BYTES>>>(
        x, Wih_f, Whh_f, bih_f, bhh_f, Wih_b, Whh_b, bih_b, bhh_b, out);
}

// round 3
// speedup vs baseline: 1.0466x; 1.0466x over previous
#include <cuda_runtime.h>
#include <cuda_fp16.h>

// Bidirectional LSTM (H=128, I=4, B=256, T=512), final hidden states only.
// out: [B, 2H] fp32.  Grid: 128 CTAs = 2 dirs x 64 batch-tiles (Bt=4).
// Thread g (0..511) owns gate row g; 4 batch elements per CTA.
// Matvec core: packed fma.rn.f32x2 with (even-k, odd-k) pair accumulators.
//   acc_b(pair) += (h[b][k], h[b][k+1]) * (w[k], w[k+1])
// Weights fp16 in SMEM (pitch 136 halves -> conflict-free LDS.128 rows),
// h fp32 in SMEM transposed per batch row (broadcast LDS.128 -> reg pairs).
// Accurate activations (ex2/rcp based), fp32 state.

#define HD    128
#define G4    512
#define TLEN  512
#define IDIM  4
#define BT    4
#define NTH   512
#define WPITCH 136   // halves per weight row (272 B: 16B-aligned, conflict-free)

// SMEM layout (bytes)
#define W_SM_BYTES   (G4 * WPITCH * 2)          // 139264
#define X_SM_BYTES   (TLEN * BT * IDIM * 4)     // 32768
#define GATE_BYTES   (G4 * 16)                  // 8192
#define H_SM_BYTES   (BT * HD * 4)              // 2048
#define X_SM_OFF     (W_SM_BYTES)
#define GATE_OFF     (W_SM_BYTES + X_SM_BYTES)
#define H_SM_OFF     (GATE_OFF + GATE_BYTES)
#define SMEM_BYTES   (H_SM_OFF + H_SM_BYTES)    // 182272

typedef unsigned long long u64;

// half2 -> f32x2 pair in one 64-bit register (2 F2F; movs dissolve in ptxas)
__device__ __forceinline__ u64 h2_to_f32x2(unsigned int w2) {
    u64 r;
    asm("{\n\t"
        ".reg .b16 lo, hi;\n\t"
        ".reg .f32 flo, fhi;\n\t"
        "mov.b32 {lo, hi}, %1;\n\t"
        "cvt.f32.f16 flo, lo;\n\t"
        "cvt.f32.f16 fhi, hi;\n\t"
        "mov.b64 %0, {flo, fhi};\n\t"
        "}" : "=l"(r) : "r"(w2));
    return r;
}

__device__ __forceinline__ void fma2(u64& d, u64 a, u64 b) {
    asm("fma.rn.f32x2 %0, %1, %2, %0;" : "+l"(d) : "l"(a), "l"(b));
}

__device__ __forceinline__ float hsum2(u64 p) {
    float lo, hi;
    asm("mov.b64 {%0, %1}, %2;" : "=f"(lo), "=f"(hi) : "l"(p));
    return lo + hi;
}

__device__ __forceinline__ float sigmoid_f(float x) {
    float e = __expf(-x);
    return __fdividef(1.0f, 1.0f + e);
}
__device__ __forceinline__ float tanh_f(float x) {
    float ax = fabsf(x);
    float e = __expf(-2.0f * ax);
    float t = __fdividef(1.0f - e, 1.0f + e);
    return copysignf(t, x);
}

__global__ void __launch_bounds__(NTH, 1)
lstm_bidir_kernel(const float* __restrict__ x,
                  const float* __restrict__ Wih_f, const float* __restrict__ Whh_f,
                  const float* __restrict__ bih_f, const float* __restrict__ bhh_f,
                  const float* __restrict__ Wih_b, const float* __restrict__ Whh_b,
                  const float* __restrict__ bih_b, const float* __restrict__ bhh_b,
                  float* __restrict__ out)
{
    extern __shared__ unsigned char smem_raw[];
    __half*  W_sm     = reinterpret_cast<__half*>(smem_raw);
    float*   x_sm     = reinterpret_cast<float*>(smem_raw + X_SM_OFF);
    float4*  gates_sm = reinterpret_cast<float4*>(smem_raw + GATE_OFF);
    float*   h_sm     = reinterpret_cast<float*>(smem_raw + H_SM_OFF); // [4][128]

    const int tid = threadIdx.x;
    const int bx  = blockIdx.x;
    const int dir = bx >> 6;            // 0 = forward, 1 = backward
    const int b_base = (bx & 63) * BT;

    const float* Wih = dir ? Wih_b : Wih_f;
    const float* Whh = dir ? Whh_b : Whh_f;
    const float* bih = dir ? bih_b : bih_f;
    const float* bhh = dir ? bhh_b : bhh_f;

    // ---- Stage Whh into SMEM as fp16 ----
    for (int idx = tid; idx < G4 * HD; idx += NTH) {
        int g = idx >> 7;
        int k = idx & 127;
        W_sm[g * WPITCH + k] = __float2half_rn(Whh[idx]);
    }
    // ---- Stage x slice: x_sm[t][b][i] ----
    for (int idx = tid; idx < BT * TLEN * IDIM; idx += NTH) {
        int b = idx >> 11;
        int r = idx & 2047;
        x_sm[(r >> 2) * (BT * IDIM) + b * IDIM + (r & 3)] =
            x[(b_base + b) * (TLEN * IDIM) + r];
    }
    const int g = tid;
    float4 wi = *reinterpret_cast<const float4*>(Wih + g * IDIM);
    float bias = bih[g] + bhh[g];

    if (tid < HD) {
        h_sm[0 * HD + tid] = 0.f;
        h_sm[1 * HD + tid] = 0.f;
        h_sm[2 * HD + tid] = 0.f;
        h_sm[3 * HD + tid] = 0.f;
    }
    float c0 = 0.f, c1 = 0.f, c2 = 0.f, c3 = 0.f;
    float h0 = 0.f, h1 = 0.f, h2 = 0.f, h3 = 0.f;
    __syncthreads();

    const __half* wrow = W_sm + g * WPITCH;

    for (int t = 0; t < TLEN; t++) {
        const int tx = dir ? (TLEN - 1 - t) : t;

        // xw + bias (I=4 folded)
        const float4* xr = reinterpret_cast<const float4*>(x_sm + tx * (BT * IDIM));
        float4 xb0 = xr[0], xb1 = xr[1], xb2 = xr[2], xb3 = xr[3];
        float s0 = fmaf(xb0.x, wi.x, fmaf(xb0.y, wi.y, fmaf(xb0.z, wi.z, fmaf(xb0.w, wi.w, bias))));
        float s1 = fmaf(xb1.x, wi.x, fmaf(xb1.y, wi.y, fmaf(xb1.z, wi.z, fmaf(xb1.w, wi.w, bias))));
        float s2 = fmaf(xb2.x, wi.x, fmaf(xb2.y, wi.y, fmaf(xb2.z, wi.z, fmaf(xb2.w, wi.w, bias))));
        float s3 = fmaf(xb3.x, wi.x, fmaf(xb3.y, wi.y, fmaf(xb3.z, wi.z, fmaf(xb3.w, wi.w, bias))));

        // Packed matvec: acc_b = (even-k sum, odd-k sum)
        u64 acc0 = 0ull, acc1 = 0ull, acc2 = 0ull, acc3 = 0ull;

        #pragma unroll
        for (int kc = 0; kc < HD; kc += 8) {
            uint4 wq = *reinterpret_cast<const uint4*>(wrow + kc);  // 8 fp16
            u64 w01 = h2_to_f32x2(wq.x);
            u64 w23 = h2_to_f32x2(wq.y);
            u64 w45 = h2_to_f32x2(wq.z);
            u64 w67 = h2_to_f32x2(wq.w);

            // batch 0
            {
                ulonglong2 hA = *reinterpret_cast<const ulonglong2*>(h_sm + 0 * HD + kc);
                ulonglong2 hB = *reinterpret_cast<const ulonglong2*>(h_sm + 0 * HD + kc + 4);
                fma2(acc0, hA.x, w01); fma2(acc0, hA.y, w23);
                fma2(acc0, hB.x, w45); fma2(acc0, hB.y, w67);
            }
            // batch 1
            {
                ulonglong2 hA = *reinterpret_cast<const ulonglong2*>(h_sm + 1 * HD + kc);
                ulonglong2 hB = *reinterpret_cast<const ulonglong2*>(h_sm + 1 * HD + kc + 4);
                fma2(acc1, hA.x, w01); fma2(acc1, hA.y, w23);
                fma2(acc1, hB.x, w45); fma2(acc1, hB.y, w67);
            }
            // batch 2
            {
                ulonglong2 hA = *reinterpret_cast<const ulonglong2*>(h_sm + 2 * HD + kc);
                ulonglong2 hB = *reinterpret_cast<const ulonglong2*>(h_sm + 2 * HD + kc + 4);
                fma2(acc2, hA.x, w01); fma2(acc2, hA.y, w23);
                fma2(acc2, hB.x, w45); fma2(acc2, hB.y, w67);
            }
            // batch 3
            {
                ulonglong2 hA = *reinterpret_cast<const ulonglong2*>(h_sm + 3 * HD + kc);
                ulonglong2 hB = *reinterpret_cast<const ulonglong2*>(h_sm + 3 * HD + kc + 4);
                fma2(acc3, hA.x, w01); fma2(acc3, hA.y, w23);
                fma2(acc3, hB.x, w45); fma2(acc3, hB.y, w67);
            }
        }

        gates_sm[g] = make_float4(s0 + hsum2(acc0), s1 + hsum2(acc1),
                                  s2 + hsum2(acc2), s3 + hsum2(acc3));
        __syncthreads();

        // Epilogue: thread j (<128) owns hidden unit j for all 4 batches.
        if (tid < HD) {
            float4 gi = gates_sm[tid];
            float4 gf = gates_sm[tid + 128];
            float4 gc = gates_sm[tid + 256];
            float4 go = gates_sm[tid + 384];
            {
                float iv = sigmoid_f(gi.x), fv = sigmoid_f(gf.x);
                float gv = tanh_f(gc.x),    ov = sigmoid_f(go.x);
                c0 = fmaf(fv, c0, iv * gv); h0 = ov * tanh_f(c0);
            }
            {
                float iv = sigmoid_f(gi.y), fv = sigmoid_f(gf.y);
                float gv = tanh_f(gc.y),    ov = sigmoid_f(go.y);
                c1 = fmaf(fv, c1, iv * gv); h1 = ov * tanh_f(c1);
            }
            {
                float iv = sigmoid_f(gi.z), fv = sigmoid_f(gf.z);
                float gv = tanh_f(gc.z),    ov = sigmoid_f(go.z);
                c2 = fmaf(fv, c2, iv * gv); h2 = ov * tanh_f(c2);
            }
            {
                float iv = sigmoid_f(gi.w), fv = sigmoid_f(gf.w);
                float gv = tanh_f(gc.w),    ov = sigmoid_f(go.w);
                c3 = fmaf(fv, c3, iv * gv); h3 = ov * tanh_f(c3);
            }
            h_sm[0 * HD + tid] = h0;
            h_sm[1 * HD + tid] = h1;
            h_sm[2 * HD + tid] = h2;
            h_sm[3 * HD + tid] = h3;
        }
        __syncthreads();
    }

    if (tid < HD) {
        const int col = dir * HD + tid;
        out[(b_base + 0) * (2 * HD) + col] = h0;
        out[(b_base + 1) * (2 * HD) + col] = h1;
        out[(b_base + 2) * (2 * HD) + col] = h2;
        out[(b_base + 3) * (2 * HD) + col] = h3;
    }
}

extern "C" void kernel_launch(void* const* d_in, const int* in_sizes, int n_in,
                              void* d_out, int out_size)
{
    const float* x     = (const float*)d_in[0];
    const float* Wih_f = (const float*)d_in[1];
    const float* Whh_f = (const float*)d_in[2];
    const float* bih_f = (const float*)d_in[3];
    const float* bhh_f = (const float*)d_in[4];
    const float* Wih_b = (const float*)d_in[5];
    const float* Whh_b = (const float*)d_in[6];
    const float* bih_b = (const float*)d_in[7];
    const float* bhh_b = (const float*)d_in[8];
    float* out = (float*)d_out;

    cudaFuncSetAttribute(lstm_bidir_kernel,
                         cudaFuncAttributeMaxDynamicSharedMemorySize, SMEM_BYTES);

    lstm_bidir_kernel<<<128, NTH, SMEM_BYTES>>>(
        x, Wih_f, Whh_f, bih_f, bhh_f, Wih_b, Whh_b, bih_b, bhh_b, out);
}

// round 4
// speedup vs baseline: 1.0472x; 1.0006x over previous
#include <cuda_runtime.h>
#include <cuda_fp16.h>

// Bidirectional LSTM (H=128, I=4, B=256, T=512), final hidden states only.
// out: [B, 2H] fp32.  Grid: 128 CTAs = 2 dirs x 64 batch-tiles (Bt=4).
// Thread g (0..511) owns gate row g; 4 batch elements per CTA.
// Matvec core: packed fma.rn.f32x2 with (even-k, odd-k) pair accumulators.
//   acc_b(pair) += (h[b][k], h[b][k+1]) * (w[k], w[k+1])
// Weights fp16 in SMEM (pitch 136 halves -> conflict-free LDS.128 rows),
// h fp32 in SMEM transposed per batch row (broadcast LDS.128 -> reg pairs).
// Accurate activations (ex2/rcp based), fp32 state.

#define HD    128
#define G4    512
#define TLEN  512
#define IDIM  4
#define BT    4
#define NTH   512
#define WPITCH 136   // halves per weight row (272 B: 16B-aligned, conflict-free)

// SMEM layout (bytes)
#define W_SM_BYTES   (G4 * WPITCH * 2)          // 139264
#define X_SM_BYTES   (TLEN * BT * IDIM * 4)     // 32768
#define GATE_BYTES   (G4 * 16)                  // 8192
#define H_SM_BYTES   (BT * HD * 4)              // 2048
#define X_SM_OFF     (W_SM_BYTES)
#define GATE_OFF     (W_SM_BYTES + X_SM_BYTES)
#define H_SM_OFF     (GATE_OFF + GATE_BYTES)
#define SMEM_BYTES   (H_SM_OFF + H_SM_BYTES)    // 182272

typedef unsigned long long u64;

// half2 -> f32x2 pair in one 64-bit register (2 F2F; movs dissolve in ptxas)
__device__ __forceinline__ u64 h2_to_f32x2(unsigned int w2) {
    u64 r;
    asm("{\n\t"
        ".reg .b16 lo, hi;\n\t"
        ".reg .f32 flo, fhi;\n\t"
        "mov.b32 {lo, hi}, %1;\n\t"
        "cvt.f32.f16 flo, lo;\n\t"
        "cvt.f32.f16 fhi, hi;\n\t"
        "mov.b64 %0, {flo, fhi};\n\t"
        "}" : "=l"(r) : "r"(w2));
    return r;
}

__device__ __forceinline__ void fma2(u64& d, u64 a, u64 b) {
    asm("fma.rn.f32x2 %0, %1, %2, %0;" : "+l"(d) : "l"(a), "l"(b));
}

__device__ __forceinline__ float hsum2(u64 p) {
    float lo, hi;
    asm("mov.b64 {%0, %1}, %2;" : "=f"(lo), "=f"(hi) : "l"(p));
    return lo + hi;
}

__device__ __forceinline__ float sigmoid_f(float x) {
    float e = __expf(-x);
    return __fdividef(1.0f, 1.0f + e);
}
__device__ __forceinline__ float tanh_f(float x) {
    float ax = fabsf(x);
    float e = __expf(-2.0f * ax);
    float t = __fdividef(1.0f - e, 1.0f + e);
    return copysignf(t, x);
}

__global__ void __launch_bounds__(NTH, 1)
lstm_bidir_kernel(const float* __restrict__ x,
                  const float* __restrict__ Wih_f, const float* __restrict__ Whh_f,
                  const float* __restrict__ bih_f, const float* __restrict__ bhh_f,
                  const float* __restrict__ Wih_b, const float* __restrict__ Whh_b,
                  const float* __restrict__ bih_b, const float* __restrict__ bhh_b,
                  float* __restrict__ out)
{
    extern __shared__ unsigned char smem_raw[];
    __half*  W_sm     = reinterpret_cast<__half*>(smem_raw);
    float*   x_sm     = reinterpret_cast<float*>(smem_raw + X_SM_OFF);
    float4*  gates_sm = reinterpret_cast<float4*>(smem_raw + GATE_OFF);
    float*   h_sm     = reinterpret_cast<float*>(smem_raw + H_SM_OFF); // [4][128]

    const int tid = threadIdx.x;
    const int bx  = blockIdx.x;
    const int dir = bx >> 6;            // 0 = forward, 1 = backward
    const int b_base = (bx & 63) * BT;

    const float* Wih = dir ? Wih_b : Wih_f;
    const float* Whh = dir ? Whh_b : Whh_f;
    const float* bih = dir ? bih_b : bih_f;
    const float* bhh = dir ? bhh_b : bhh_f;

    // ---- Stage Whh into SMEM as fp16 ----
    for (int idx = tid; idx < G4 * HD; idx += NTH) {
        int g = idx >> 7;
        int k = idx & 127;
        W_sm[g * WPITCH + k] = __float2half_rn(Whh[idx]);
    }
    // ---- Stage x slice: x_sm[t][b][i] ----
    for (int idx = tid; idx < BT * TLEN * IDIM; idx += NTH) {
        int b = idx >> 11;
        int r = idx & 2047;
        x_sm[(r >> 2) * (BT * IDIM) + b * IDIM + (r & 3)] =
            x[(b_base + b) * (TLEN * IDIM) + r];
    }
    const int g = tid;
    float4 wi = *reinterpret_cast<const float4*>(Wih + g * IDIM);
    float bias = bih[g] + bhh[g];

    if (tid < HD) {
        h_sm[0 * HD + tid] = 0.f;
        h_sm[1 * HD + tid] = 0.f;
        h_sm[2 * HD + tid] = 0.f;
        h_sm[3 * HD + tid] = 0.f;
    }
    float c0 = 0.f, c1 = 0.f, c2 = 0.f, c3 = 0.f;
    float h0 = 0.f, h1 = 0.f, h2 = 0.f, h3 = 0.f;
    __syncthreads();

    const __half* wrow = W_sm + g * WPITCH;

    for (int t = 0; t < TLEN; t++) {
        const int tx = dir ? (TLEN - 1 - t) : t;

        // xw + bias (I=4 folded)
        const float4* xr = reinterpret_cast<const float4*>(x_sm + tx * (BT * IDIM));
        float4 xb0 = xr[0], xb1 = xr[1], xb2 = xr[2], xb3 = xr[3];
        float s0 = fmaf(xb0.x, wi.x, fmaf(xb0.y, wi.y, fmaf(xb0.z, wi.z, fmaf(xb0.w, wi.w, bias))));
        float s1 = fmaf(xb1.x, wi.x, fmaf(xb1.y, wi.y, fmaf(xb1.z, wi.z, fmaf(xb1.w, wi.w, bias))));
        float s2 = fmaf(xb2.x, wi.x, fmaf(xb2.y, wi.y, fmaf(xb2.z, wi.z, fmaf(xb2.w, wi.w, bias))));
        float s3 = fmaf(xb3.x, wi.x, fmaf(xb3.y, wi.y, fmaf(xb3.z, wi.z, fmaf(xb3.w, wi.w, bias))));

        // Packed matvec: acc_b = (even-k sum, odd-k sum)
        u64 acc0 = 0ull, acc1 = 0ull, acc2 = 0ull, acc3 = 0ull;

        #pragma unroll
        for (int kc = 0; kc < HD; kc += 8) {
            uint4 wq = *reinterpret_cast<const uint4*>(wrow + kc);  // 8 fp16
            u64 w01 = h2_to_f32x2(wq.x);
            u64 w23 = h2_to_f32x2(wq.y);
            u64 w45 = h2_to_f32x2(wq.z);
            u64 w67 = h2_to_f32x2(wq.w);

            // batch 0
            {
                ulonglong2 hA = *reinterpret_cast<const ulonglong2*>(h_sm + 0 * HD + kc);
                ulonglong2 hB = *reinterpret_cast<const ulonglong2*>(h_sm + 0 * HD + kc + 4);
                fma2(acc0, hA.x, w01); fma2(acc0, hA.y, w23);
                fma2(acc0, hB.x, w45); fma2(acc0, hB.y, w67);
            }
            // batch 1
            {
                ulonglong2 hA = *reinterpret_cast<const ulonglong2*>(h_sm + 1 * HD + kc);
                ulonglong2 hB = *reinterpret_cast<const ulonglong2*>(h_sm + 1 * HD + kc + 4);
                fma2(acc1, hA.x, w01); fma2(acc1, hA.y, w23);
                fma2(acc1, hB.x, w45); fma2(acc1, hB.y, w67);
            }
            // batch 2
            {
                ulonglong2 hA = *reinterpret_cast<const ulonglong2*>(h_sm + 2 * HD + kc);
                ulonglong2 hB = *reinterpret_cast<const ulonglong2*>(h_sm + 2 * HD + kc + 4);
                fma2(acc2, hA.x, w01); fma2(acc2, hA.y, w23);
                fma2(acc2, hB.x, w45); fma2(acc2, hB.y, w67);
            }
            // batch 3
            {
                ulonglong2 hA = *reinterpret_cast<const ulonglong2*>(h_sm + 3 * HD + kc);
                ulonglong2 hB = *reinterpret_cast<const ulonglong2*>(h_sm + 3 * HD + kc + 4);
                fma2(acc3, hA.x, w01); fma2(acc3, hA.y, w23);
                fma2(acc3, hB.x, w45); fma2(acc3, hB.y, w67);
            }
        }

        gates_sm[g] = make_float4(s0 + hsum2(acc0), s1 + hsum2(acc1),
                                  s2 + hsum2(acc2), s3 + hsum2(acc3));
        __syncthreads();

        // Epilogue: thread j (<128) owns hidden unit j for all 4 batches.
        if (tid < HD) {
            float4 gi = gates_sm[tid];
            float4 gf = gates_sm[tid + 128];
            float4 gc = gates_sm[tid + 256];
            float4 go = gates_sm[tid + 384];
            {
                float iv = sigmoid_f(gi.x), fv = sigmoid_f(gf.x);
                float gv = tanh_f(gc.x),    ov = sigmoid_f(go.x);
                c0 = fmaf(fv, c0, iv * gv); h0 = ov * tanh_f(c0);
            }
            {
                float iv = sigmoid_f(gi.y), fv = sigmoid_f(gf.y);
                float gv = tanh_f(gc.y),    ov = sigmoid_f(go.y);
                c1 = fmaf(fv, c1, iv * gv); h1 = ov * tanh_f(c1);
            }
            {
                float iv = sigmoid_f(gi.z), fv = sigmoid_f(gf.z);
                float gv = tanh_f(gc.z),    ov = sigmoid_f(go.z);
                c2 = fmaf(fv, c2, iv * gv); h2 = ov * tanh_f(c2);
            }
            {
                float iv = sigmoid_f(gi.w), fv = sigmoid_f(gf.w);
                float gv = tanh_f(gc.w),    ov = sigmoid_f(go.w);
                c3 = fmaf(fv, c3, iv * gv); h3 = ov * tanh_f(c3);
            }
            h_sm[0 * HD + tid] = h0;
            h_sm[1 * HD + tid] = h1;
            h_sm[2 * HD + tid] = h2;
            h_sm[3 * HD + tid] = h3;
        }
        __syncthreads();
    }

    if (tid < HD) {
        const int col = dir * HD + tid;
        out[(b_base + 0) * (2 * HD) + col] = h0;
        out[(b_base + 1) * (2 * HD) + col] = h1;
        out[(b_base + 2) * (2 * HD) + col] = h2;
        out[(b_base + 3) * (2 * HD) + col] = h3;
    }
}

extern "C" void kernel_launch(void* const* d_in, const int* in_sizes, int n_in,
                              void* d_out, int out_size)
{
    const float* x     = (const float*)d_in[0];
    const float* Wih_f = (const float*)d_in[1];
    const float* Whh_f = (const float*)d_in[2];
    const float* bih_f = (const float*)d_in[3];
    const float* bhh_f = (const float*)d_in[4];
    const float* Wih_b = (const float*)d_in[5];
    const float* Whh_b = (const float*)d_in[6];
    const float* bih_b = (const float*)d_in[7];
    const float* bhh_b = (const float*)d_in[8];
    float* out = (float*)d_out;

    cudaFuncSetAttribute(lstm_bidir_kernel,
                         cudaFuncAttributeMaxDynamicSharedMemorySize, SMEM_BYTES);

    lstm_bidir_kernel<<<128, NTH, SMEM_BYTES>>>(
        x, Wih_f, Whh_f, bih_f, bhh_f, Wih_b, Whh_b, bih_b, bhh_b, out);
}

// round 6
// speedup vs baseline: 4.8561x; 4.6371x over previous
#include <cuda_runtime.h>
#include <cuda_fp16.h>
#include <cstdint>

// Bidirectional LSTM (H=128, I=4, B=256, T=512), final h only. out [B,2H] fp32.
// Grid: 128 CTAs = 2 dirs x 64 batch-tiles (BT=4), 256 threads (8 warps).
// Weight-stationary register MMA: warp w holds Whh rows [w*64,(w+1)*64) as
// m16n8k16 A fragments in registers (loaded once). Per step:
//   gates[512,8] = Whh_fp16 @ h_fp16^T  (N=8: batches 0-3 real, 4-7 zero)
// via 4 m-tiles x 8 k-chunks of mma.sync.m16n8k16.f32.f16.f16.f32 per warp.
// Epilogue: thread u owns unit j=u&127, batches 2bp,2bp+1 (bp=u>>7); fp32 xw,
// accurate exp-based activations, fp32 c/h; h -> fp16 -> B buffer in SMEM.

#define HD     128
#define TLEN   512
#define BT     4
#define NTH    256
#define GPITCH 10        // gates row pitch in floats (40 B)
#define HPITCH 136       // h row pitch in halves (272 B, conflict-free)

// dynamic SMEM layout (bytes)
#define SM_GATES  0
#define GATES_B   (512 * GPITCH * 4)            // 20480
#define SM_H      GATES_B                        // 20480
#define H_B       (8 * HPITCH * 2)               // 2176
#define SM_X      (SM_GATES + GATES_B + H_B)     // 22656
#define X_B       (TLEN * BT * 4 * 4)            // 32768
#define SM_TOTAL  (SM_X + X_B)                   // 55424

__device__ __forceinline__ void mma16816(float* d, const uint32_t* a,
                                         uint32_t b0, uint32_t b1) {
    asm volatile(
        "mma.sync.aligned.m16n8k16.row.col.f32.f16.f16.f32 "
        "{%0,%1,%2,%3}, {%4,%5,%6,%7}, {%8,%9}, {%0,%1,%2,%3};"
        : "+f"(d[0]), "+f"(d[1]), "+f"(d[2]), "+f"(d[3])
        : "r"(a[0]), "r"(a[1]), "r"(a[2]), "r"(a[3]), "r"(b0), "r"(b1));
}

__device__ __forceinline__ uint32_t packh2(float lo, float hi) {
    __half2 h = __floats2half2_rn(lo, hi);
    return *reinterpret_cast<uint32_t*>(&h);
}
__device__ __forceinline__ float sigmoid_f(float x) {
    float e = __expf(-x);
    return __fdividef(1.0f, 1.0f + e);
}
__device__ __forceinline__ float tanh_f(float x) {
    float ax = fabsf(x);
    float e = __expf(-2.0f * ax);
    float t = __fdividef(1.0f - e, 1.0f + e);
    return copysignf(t, x);
}

__global__ void __launch_bounds__(NTH, 1)
lstm_mma_kernel(const float* __restrict__ x,
                const float* __restrict__ Wih_f, const float* __restrict__ Whh_f,
                const float* __restrict__ bih_f, const float* __restrict__ bhh_f,
                const float* __restrict__ Wih_b, const float* __restrict__ Whh_b,
                const float* __restrict__ bih_b, const float* __restrict__ bhh_b,
                float* __restrict__ out)
{
    extern __shared__ unsigned char smem[];
    float*  gates_sm = reinterpret_cast<float*>(smem + SM_GATES);
    __half* h_sm     = reinterpret_cast<__half*>(smem + SM_H);
    float*  x_sm     = reinterpret_cast<float*>(smem + SM_X);

    const int tid = threadIdx.x;
    const int w   = tid >> 5;          // warp 0..7
    const int l   = tid & 31;
    const int gid = l >> 2;            // 0..7
    const int tig = l & 3;             // 0..3
    const int bx  = blockIdx.x;
    const int dir = bx >> 6;
    const int b_base = (bx & 63) * BT;

    const float* Wih = dir ? Wih_b : Wih_f;
    const float* Whh = dir ? Whh_b : Whh_f;
    const float* bih = dir ? bih_b : bih_f;
    const float* bhh = dir ? bhh_b : bhh_f;

    // ---- Load stationary A fragments: warp w owns rows [w*64, w*64+64) ----
    // a[mt][kc][0..3]: rows (r0, r0+8) x k (k0,k0+1, k0+8,k0+9), r0=w*64+mt*16+gid
    uint32_t A[4][8][4];
    #pragma unroll
    for (int mt = 0; mt < 4; mt++) {
        const int r0 = w * 64 + mt * 16 + gid;
        const float* row0 = Whh + r0 * HD;
        const float* row1 = Whh + (r0 + 8) * HD;
        #pragma unroll
        for (int kc = 0; kc < 8; kc++) {
            const int k0 = kc * 16 + tig * 2;
            float2 p00 = *reinterpret_cast<const float2*>(row0 + k0);
            float2 p10 = *reinterpret_cast<const float2*>(row1 + k0);
            float2 p01 = *reinterpret_cast<const float2*>(row0 + k0 + 8);
            float2 p11 = *reinterpret_cast<const float2*>(row1 + k0 + 8);
            A[mt][kc][0] = packh2(p00.x, p00.y);
            A[mt][kc][1] = packh2(p10.x, p10.y);
            A[mt][kc][2] = packh2(p01.x, p01.y);
            A[mt][kc][3] = packh2(p11.x, p11.y);
        }
    }

    // ---- Zero h buffer (8 rows x HPITCH halves; rows 4-7 stay zero) ----
    for (int i = tid; i < (8 * HPITCH) / 2; i += NTH)
        reinterpret_cast<uint32_t*>(h_sm)[i] = 0u;

    // ---- Stage x slice: x_sm[t][b][i] ----
    for (int idx = tid; idx < BT * TLEN * 4; idx += NTH) {
        int b = idx >> 11, r = idx & 2047;
        x_sm[(r >> 2) * (BT * 4) + b * 4 + (r & 3)] = x[(b_base + b) * (TLEN * 4) + r];
    }

    // ---- Epilogue constants: thread u owns unit j, batches 2bp, 2bp+1 ----
    const int j  = tid & 127;
    const int bp = tid >> 7;
    float4 wi[4];
    float  bias[4];
    #pragma unroll
    for (int gt = 0; gt < 4; gt++) {
        int g = gt * 128 + j;
        wi[gt]   = *reinterpret_cast<const float4*>(Wih + g * 4);
        bias[gt] = bih[g] + bhh[g];
    }
    float cA = 0.f, cB = 0.f, hA = 0.f, hB = 0.f;

    const __half* hrow = h_sm + gid * HPITCH + tig * 2;   // B frag base (n=gid)
    __syncthreads();

    for (int t = 0; t < TLEN; t++) {
        const int tx = dir ? (TLEN - 1 - t) : t;

        // ---- B fragments from h_sm ----
        uint32_t b0[8], b1[8];
        #pragma unroll
        for (int kc = 0; kc < 8; kc++) {
            b0[kc] = *reinterpret_cast<const uint32_t*>(hrow + kc * 16);
            b1[kc] = *reinterpret_cast<const uint32_t*>(hrow + kc * 16 + 8);
        }

        // ---- MMA: 4 m-tiles x 8 k-chunks ----
        float acc[4][4];
        #pragma unroll
        for (int mt = 0; mt < 4; mt++) {
            acc[mt][0] = acc[mt][1] = acc[mt][2] = acc[mt][3] = 0.f;
            #pragma unroll
            for (int kc = 0; kc < 8; kc++)
                mma16816(acc[mt], A[mt][kc], b0[kc], b1[kc]);
        }

        // ---- Dump gates (cols 0-3 live in lanes tig<2) ----
        if (tig < 2) {
            #pragma unroll
            for (int mt = 0; mt < 4; mt++) {
                const int r0 = w * 64 + mt * 16 + gid;
                *reinterpret_cast<float2*>(gates_sm + r0 * GPITCH + tig * 2) =
                    make_float2(acc[mt][0], acc[mt][1]);
                *reinterpret_cast<float2*>(gates_sm + (r0 + 8) * GPITCH + tig * 2) =
                    make_float2(acc[mt][2], acc[mt][3]);
            }
        }
        __syncthreads();

        // ---- Epilogue: unit j, batches 2bp, 2bp+1 ----
        float2 gi = *reinterpret_cast<const float2*>(gates_sm + (0 * 128 + j) * GPITCH + bp * 2);
        float2 gf = *reinterpret_cast<const float2*>(gates_sm + (1 * 128 + j) * GPITCH + bp * 2);
        float2 gg = *reinterpret_cast<const float2*>(gates_sm + (2 * 128 + j) * GPITCH + bp * 2);
        float2 go = *reinterpret_cast<const float2*>(gates_sm + (3 * 128 + j) * GPITCH + bp * 2);

        const float* xr = x_sm + tx * (BT * 4) + bp * 8;
        float4 xa = *reinterpret_cast<const float4*>(xr);
        float4 xb = *reinterpret_cast<const float4*>(xr + 4);

        #pragma unroll
        for (int gt = 0; gt < 4; gt++) {
            float xwA = fmaf(xa.x, wi[gt].x, fmaf(xa.y, wi[gt].y,
                        fmaf(xa.z, wi[gt].z, fmaf(xa.w, wi[gt].w, bias[gt]))));
            float xwB = fmaf(xb.x, wi[gt].x, fmaf(xb.y, wi[gt].y,
                        fmaf(xb.z, wi[gt].z, fmaf(xb.w, wi[gt].w, bias[gt]))));
            if (gt == 0) { gi.x += xwA; gi.y += xwB; }
            if (gt == 1) { gf.x += xwA; gf.y += xwB; }
            if (gt == 2) { gg.x += xwA; gg.y += xwB; }
            if (gt == 3) { go.x += xwA; go.y += xwB; }
        }

        {
            float iv = sigmoid_f(gi.x), fv = sigmoid_f(gf.x);
            float gv = tanh_f(gg.x),    ov = sigmoid_f(go.x);
            cA = fmaf(fv, cA, iv * gv); hA = ov * tanh_f(cA);
        }
        {
            float iv = sigmoid_f(gi.y), fv = sigmoid_f(gf.y);
            float gv = tanh_f(gg.y),    ov = sigmoid_f(go.y);
            cB = fmaf(fv, cB, iv * gv); hB = ov * tanh_f(cB);
        }
        h_sm[(bp * 2 + 0) * HPITCH + j] = __float2half_rn(hA);
        h_sm[(bp * 2 + 1) * HPITCH + j] = __float2half_rn(hB);
        __syncthreads();
    }

    // ---- Output: out[b][dir*128 + j], fp32 from registers ----
    out[(b_base + bp * 2 + 0) * (2 * HD) + dir * HD + j] = hA;
    out[(b_base + bp * 2 + 1) * (2 * HD) + dir * HD + j] = hB;
}

extern "C" void kernel_launch(void* const* d_in, const int* in_sizes, int n_in,
                              void* d_out, int out_size)
{
    const float* x     = (const float*)d_in[0];
    const float* Wih_f = (const float*)d_in[1];
    const float* Whh_f = (const float*)d_in[2];
    const float* bih_f = (const float*)d_in[3];
    const float* bhh_f = (const float*)d_in[4];
    const float* Wih_b = (const float*)d_in[5];
    const float* Whh_b = (const float*)d_in[6];
    const float* bih_b = (const float*)d_in[7];
    const float* bhh_b = (const float*)d_in[8];
    float* out = (float*)d_out;

    cudaFuncSetAttribute(lstm_mma_kernel,
                         cudaFuncAttributeMaxDynamicSharedMemorySize, SM_TOTAL);

    lstm_mma_kernel<<<128, NTH, SM_TOTAL>>>(
        x, Wih_f, Whh_f, bih_f, bhh_f, Wih_b, Whh_b, bih_b, bhh_b, out);
}

// round 7
// speedup vs baseline: 4.8799x; 1.0049x over previous
#include <cuda_runtime.h>
#include <cuda_fp16.h>
#include <cstdint>

// Bidirectional LSTM (H=128, I=4, B=256, T=512), final h only. out [B,2H] fp32.
// Grid: 128 CTAs = 2 dirs x 64 batch-tiles (BT=4), 256 threads (8 warps).
// Weight-stationary register MMA: warp w holds Whh rows [w*64,(w+1)*64) as
// m16n8k16 A fragments in registers (loaded once). Per step:
//   gates[512,8] = Whh_fp16 @ h_fp16^T  (N=8: batches 0-3 real, 4-7 zero)
// via 4 m-tiles x 8 k-chunks of mma.sync.m16n8k16.f32.f16.f16.f32 per warp.
// Epilogue: thread u owns unit j=u&127, batches 2bp,2bp+1 (bp=u>>7); fp32 xw,
// accurate exp-based activations, fp32 c/h; h -> fp16 -> B buffer in SMEM.

#define HD     128
#define TLEN   512
#define BT     4
#define NTH    256
#define GPITCH 10        // gates row pitch in floats (40 B)
#define HPITCH 136       // h row pitch in halves (272 B, conflict-free)

// dynamic SMEM layout (bytes)
#define SM_GATES  0
#define GATES_B   (512 * GPITCH * 4)            // 20480
#define SM_H      GATES_B                        // 20480
#define H_B       (8 * HPITCH * 2)               // 2176
#define SM_X      (SM_GATES + GATES_B + H_B)     // 22656
#define X_B       (TLEN * BT * 4 * 4)            // 32768
#define SM_TOTAL  (SM_X + X_B)                   // 55424

__device__ __forceinline__ void mma16816(float* d, const uint32_t* a,
                                         uint32_t b0, uint32_t b1) {
    asm volatile(
        "mma.sync.aligned.m16n8k16.row.col.f32.f16.f16.f32 "
        "{%0,%1,%2,%3}, {%4,%5,%6,%7}, {%8,%9}, {%0,%1,%2,%3};"
        : "+f"(d[0]), "+f"(d[1]), "+f"(d[2]), "+f"(d[3])
        : "r"(a[0]), "r"(a[1]), "r"(a[2]), "r"(a[3]), "r"(b0), "r"(b1));
}

__device__ __forceinline__ uint32_t packh2(float lo, float hi) {
    __half2 h = __floats2half2_rn(lo, hi);
    return *reinterpret_cast<uint32_t*>(&h);
}
__device__ __forceinline__ float sigmoid_f(float x) {
    float e = __expf(-x);
    return __fdividef(1.0f, 1.0f + e);
}
__device__ __forceinline__ float tanh_f(float x) {
    float ax = fabsf(x);
    float e = __expf(-2.0f * ax);
    float t = __fdividef(1.0f - e, 1.0f + e);
    return copysignf(t, x);
}

__global__ void __launch_bounds__(NTH, 1)
lstm_mma_kernel(const float* __restrict__ x,
                const float* __restrict__ Wih_f, const float* __restrict__ Whh_f,
                const float* __restrict__ bih_f, const float* __restrict__ bhh_f,
                const float* __restrict__ Wih_b, const float* __restrict__ Whh_b,
                const float* __restrict__ bih_b, const float* __restrict__ bhh_b,
                float* __restrict__ out)
{
    extern __shared__ unsigned char smem[];
    float*  gates_sm = reinterpret_cast<float*>(smem + SM_GATES);
    __half* h_sm     = reinterpret_cast<__half*>(smem + SM_H);
    float*  x_sm     = reinterpret_cast<float*>(smem + SM_X);

    const int tid = threadIdx.x;
    const int w   = tid >> 5;          // warp 0..7
    const int l   = tid & 31;
    const int gid = l >> 2;            // 0..7
    const int tig = l & 3;             // 0..3
    const int bx  = blockIdx.x;
    const int dir = bx >> 6;
    const int b_base = (bx & 63) * BT;

    const float* Wih = dir ? Wih_b : Wih_f;
    const float* Whh = dir ? Whh_b : Whh_f;
    const float* bih = dir ? bih_b : bih_f;
    const float* bhh = dir ? bhh_b : bhh_f;

    // ---- Load stationary A fragments: warp w owns rows [w*64, w*64+64) ----
    // a[mt][kc][0..3]: rows (r0, r0+8) x k (k0,k0+1, k0+8,k0+9), r0=w*64+mt*16+gid
    uint32_t A[4][8][4];
    #pragma unroll
    for (int mt = 0; mt < 4; mt++) {
        const int r0 = w * 64 + mt * 16 + gid;
        const float* row0 = Whh + r0 * HD;
        const float* row1 = Whh + (r0 + 8) * HD;
        #pragma unroll
        for (int kc = 0; kc < 8; kc++) {
            const int k0 = kc * 16 + tig * 2;
            float2 p00 = *reinterpret_cast<const float2*>(row0 + k0);
            float2 p10 = *reinterpret_cast<const float2*>(row1 + k0);
            float2 p01 = *reinterpret_cast<const float2*>(row0 + k0 + 8);
            float2 p11 = *reinterpret_cast<const float2*>(row1 + k0 + 8);
            A[mt][kc][0] = packh2(p00.x, p00.y);
            A[mt][kc][1] = packh2(p10.x, p10.y);
            A[mt][kc][2] = packh2(p01.x, p01.y);
            A[mt][kc][3] = packh2(p11.x, p11.y);
        }
    }

    // ---- Zero h buffer (8 rows x HPITCH halves; rows 4-7 stay zero) ----
    for (int i = tid; i < (8 * HPITCH) / 2; i += NTH)
        reinterpret_cast<uint32_t*>(h_sm)[i] = 0u;

    // ---- Stage x slice: x_sm[t][b][i] ----
    for (int idx = tid; idx < BT * TLEN * 4; idx += NTH) {
        int b = idx >> 11, r = idx & 2047;
        x_sm[(r >> 2) * (BT * 4) + b * 4 + (r & 3)] = x[(b_base + b) * (TLEN * 4) + r];
    }

    // ---- Epilogue constants: thread u owns unit j, batches 2bp, 2bp+1 ----
    const int j  = tid & 127;
    const int bp = tid >> 7;
    float4 wi[4];
    float  bias[4];
    #pragma unroll
    for (int gt = 0; gt < 4; gt++) {
        int g = gt * 128 + j;
        wi[gt]   = *reinterpret_cast<const float4*>(Wih + g * 4);
        bias[gt] = bih[g] + bhh[g];
    }
    float cA = 0.f, cB = 0.f, hA = 0.f, hB = 0.f;

    const __half* hrow = h_sm + gid * HPITCH + tig * 2;   // B frag base (n=gid)
    __syncthreads();

    for (int t = 0; t < TLEN; t++) {
        const int tx = dir ? (TLEN - 1 - t) : t;

        // ---- B fragments from h_sm ----
        uint32_t b0[8], b1[8];
        #pragma unroll
        for (int kc = 0; kc < 8; kc++) {
            b0[kc] = *reinterpret_cast<const uint32_t*>(hrow + kc * 16);
            b1[kc] = *reinterpret_cast<const uint32_t*>(hrow + kc * 16 + 8);
        }

        // ---- MMA: 4 m-tiles x 8 k-chunks ----
        float acc[4][4];
        #pragma unroll
        for (int mt = 0; mt < 4; mt++) {
            acc[mt][0] = acc[mt][1] = acc[mt][2] = acc[mt][3] = 0.f;
            #pragma unroll
            for (int kc = 0; kc < 8; kc++)
                mma16816(acc[mt], A[mt][kc], b0[kc], b1[kc]);
        }

        // ---- Dump gates (cols 0-3 live in lanes tig<2) ----
        if (tig < 2) {
            #pragma unroll
            for (int mt = 0; mt < 4; mt++) {
                const int r0 = w * 64 + mt * 16 + gid;
                *reinterpret_cast<float2*>(gates_sm + r0 * GPITCH + tig * 2) =
                    make_float2(acc[mt][0], acc[mt][1]);
                *reinterpret_cast<float2*>(gates_sm + (r0 + 8) * GPITCH + tig * 2) =
                    make_float2(acc[mt][2], acc[mt][3]);
            }
        }
        __syncthreads();

        // ---- Epilogue: unit j, batches 2bp, 2bp+1 ----
        float2 gi = *reinterpret_cast<const float2*>(gates_sm + (0 * 128 + j) * GPITCH + bp * 2);
        float2 gf = *reinterpret_cast<const float2*>(gates_sm + (1 * 128 + j) * GPITCH + bp * 2);
        float2 gg = *reinterpret_cast<const float2*>(gates_sm + (2 * 128 + j) * GPITCH + bp * 2);
        float2 go = *reinterpret_cast<const float2*>(gates_sm + (3 * 128 + j) * GPITCH + bp * 2);

        const float* xr = x_sm + tx * (BT * 4) + bp * 8;
        float4 xa = *reinterpret_cast<const float4*>(xr);
        float4 xb = *reinterpret_cast<const float4*>(xr + 4);

        #pragma unroll
        for (int gt = 0; gt < 4; gt++) {
            float xwA = fmaf(xa.x, wi[gt].x, fmaf(xa.y, wi[gt].y,
                        fmaf(xa.z, wi[gt].z, fmaf(xa.w, wi[gt].w, bias[gt]))));
            float xwB = fmaf(xb.x, wi[gt].x, fmaf(xb.y, wi[gt].y,
                        fmaf(xb.z, wi[gt].z, fmaf(xb.w, wi[gt].w, bias[gt]))));
            if (gt == 0) { gi.x += xwA; gi.y += xwB; }
            if (gt == 1) { gf.x += xwA; gf.y += xwB; }
            if (gt == 2) { gg.x += xwA; gg.y += xwB; }
            if (gt == 3) { go.x += xwA; go.y += xwB; }
        }

        {
            float iv = sigmoid_f(gi.x), fv = sigmoid_f(gf.x);
            float gv = tanh_f(gg.x),    ov = sigmoid_f(go.x);
            cA = fmaf(fv, cA, iv * gv); hA = ov * tanh_f(cA);
        }
        {
            float iv = sigmoid_f(gi.y), fv = sigmoid_f(gf.y);
            float gv = tanh_f(gg.y),    ov = sigmoid_f(go.y);
            cB = fmaf(fv, cB, iv * gv); hB = ov * tanh_f(cB);
        }
        h_sm[(bp * 2 + 0) * HPITCH + j] = __float2half_rn(hA);
        h_sm[(bp * 2 + 1) * HPITCH + j] = __float2half_rn(hB);
        __syncthreads();
    }

    // ---- Output: out[b][dir*128 + j], fp32 from registers ----
    out[(b_base + bp * 2 + 0) * (2 * HD) + dir * HD + j] = hA;
    out[(b_base + bp * 2 + 1) * (2 * HD) + dir * HD + j] = hB;
}

extern "C" void kernel_launch(void* const* d_in, const int* in_sizes, int n_in,
                              void* d_out, int out_size)
{
    const float* x     = (const float*)d_in[0];
    const float* Wih_f = (const float*)d_in[1];
    const float* Whh_f = (const float*)d_in[2];
    const float* bih_f = (const float*)d_in[3];
    const float* bhh_f = (const float*)d_in[4];
    const float* Wih_b = (const float*)d_in[5];
    const float* Whh_b = (const float*)d_in[6];
    const float* bih_b = (const float*)d_in[7];
    const float* bhh_b = (const float*)d_in[8];
    float* out = (float*)d_out;

    cudaFuncSetAttribute(lstm_mma_kernel,
                         cudaFuncAttributeMaxDynamicSharedMemorySize, SM_TOTAL);

    lstm_mma_kernel<<<128, NTH, SM_TOTAL>>>(
        x, Wih_f, Whh_f, bih_f, bhh_f, Wih_b, Whh_b, bih_b, bhh_b, out);
}